// round 12
// baseline (speedup 1.0000x reference)
#include <cuda_runtime.h>
#include <cuda_fp16.h>
#include <cstdint>
#include <math.h>

#define NN   50000
#define EE   800000
#define DIMD 128
#define CATD 512
#define HIDD 512

// ---------------- scratch (device globals; no allocations allowed) ----------
__device__ __align__(16) __half g_cath[(size_t)NN * CATD];  // [h|msg|msg2|msg3] half
__device__ __align__(16) __half g_fh[(size_t)NN * HIDD];    // gelu(...) half
__device__ __align__(16) __half g_xh[(size_t)NN * DIMD];
__device__ __align__(16) __half g_fcwh[DIMD * DIMD];
__device__ __align__(16) __half g_w1h[HIDD * CATD];
__device__ __align__(16) __half g_w2h[DIMD * HIDD];
__device__ __align__(16) float  g_suv[NN * 16];             // su[0..7], sv[8..15]
__device__ __align__(16) float  g_ex[(size_t)EE * 8];       // exp scores, SLOT order
__device__ float g_norm[EE];
__device__ int   g_din[NN];
__device__ int   g_dout[NN];
__device__ int   g_rowstart[NN + 1];
__device__ int   g_cursor[NN];
__device__ int   g_ssrc[EE];

__device__ __forceinline__ void cpa16(uint32_t dst, const void* src, int pbytes) {
    asm volatile("cp.async.cg.shared.global [%0], [%1], 16, %2;"
                 :: "r"(dst), "l"(src), "r"(pbytes));
}
__device__ __forceinline__ void cpa_commit() {
    asm volatile("cp.async.commit_group;");
}
template <int NG>
__device__ __forceinline__ void cpa_wait() {
    asm volatile("cp.async.wait_group %0;" :: "n"(NG));
}

// ---------------- fp16 mma.sync GEMM: C = A[M,K] @ B[N,K]^T + bias ----------
// CTA 128(M) x NT(N), K-chunk 64 halves, 4-stage cp.async pipeline, 1 sync/chunk.
#define KCH   64
#define LDS_P 72      // halves per row (64 + 8 pad); conflict-free frag LDS
#define NSTG  4

template <int NT, bool GELU, bool F32OUT, bool HOUT>
__global__ __launch_bounds__(256, 1) void gemm_h(
    const __half* __restrict__ A, int lda,
    const __half* __restrict__ B, int ldb,
    const float* __restrict__ bias,
    float* __restrict__ Cf, int ldcf,
    __half* __restrict__ Ch, int ldch,
    int M, int K)
{
    constexpr int ASZ = 128 * LDS_P;         // halves per stage
    constexpr int BSZ = NT  * LDS_P;
    constexpr int NJ2 = NT / 32;             // b-frag count (4 or 8)
    extern __shared__ __half smh[];

    const int tid  = threadIdx.x;
    const int wid  = tid >> 5, lane = tid & 31;
    const int g    = lane >> 2;
    const int tg   = lane & 3;
    const int m0   = blockIdx.y * 128;
    const int n0   = blockIdx.x * NT;
    const int mw   = (wid >> 2) * 64;
    const int nw   = (wid & 3) * (NT / 4);

    float c[4][NJ2][4];
#pragma unroll
    for (int i = 0; i < 4; i++)
#pragma unroll
        for (int j = 0; j < NJ2; j++)
#pragma unroll
            for (int q = 0; q < 4; q++) c[i][j][q] = 0.f;

    const int KC = K / KCH;

    auto stage = [&](int cc) {
        if (cc < KC) {
            const int kc = cc * KCH;
            __half* sA = smh + (cc % NSTG) * (ASZ + BSZ);
            __half* sB = sA + ASZ;
            uint32_t sAu = (uint32_t)__cvta_generic_to_shared(sA);
            uint32_t sBu = (uint32_t)__cvta_generic_to_shared(sB);
#pragma unroll
            for (int it = 0; it < 4; it++) {           // 128 rows x 8x16B
                int q   = tid + it * 256;
                int row = q >> 3;
                int kq  = (q & 7) << 3;                // half offset
                int m   = m0 + row;
                int ok  = (m < M) ? 16 : 0;
                const __half* srcp = &A[(size_t)(ok ? m : 0) * lda + kc + kq];
                cpa16(sAu + (row * LDS_P + kq) * 2, srcp, ok);
            }
#pragma unroll
            for (int it = 0; it < NT / 32; it++) {     // NT rows x 8x16B
                int q   = tid + it * 256;
                int row = q >> 3;
                int kq  = (q & 7) << 3;
                cpa16(sBu + (row * LDS_P + kq) * 2,
                      &B[(size_t)(n0 + row) * ldb + kc + kq], 16);
            }
        }
        cpa_commit();
    };

#pragma unroll
    for (int s = 0; s < NSTG - 1; s++) stage(s);

    for (int cch = 0; cch < KC; cch++) {
        cpa_wait<NSTG - 2>();
        __syncthreads();

        const __half* sA = smh + (cch % NSTG) * (ASZ + BSZ);
        const __half* sB = sA + ASZ;
        const uint32_t* uA = (const uint32_t*)sA;      // 2 halves per u32
        const uint32_t* uB = (const uint32_t*)sB;
#pragma unroll
        for (int ks = 0; ks < KCH / 16; ks++) {        // 4 k16 steps
            uint32_t a[4][4], b[NJ2][2];
#pragma unroll
            for (int i = 0; i < 4; i++) {
                int r  = (mw + i * 16 + g) * (LDS_P / 2) + ks * 8 + tg;
                a[i][0] = uA[r];
                a[i][1] = uA[r + 8 * (LDS_P / 2)];
                a[i][2] = uA[r + 4];
                a[i][3] = uA[r + 8 * (LDS_P / 2) + 4];
            }
#pragma unroll
            for (int j = 0; j < NJ2; j++) {
                int r = (nw + j * 8 + g) * (LDS_P / 2) + ks * 8 + tg;
                b[j][0] = uB[r];
                b[j][1] = uB[r + 4];
            }
#pragma unroll
            for (int i = 0; i < 4; i++)
#pragma unroll
                for (int j = 0; j < NJ2; j++) {
                    asm volatile(
                        "mma.sync.aligned.m16n8k16.row.col.f32.f16.f16.f32 "
                        "{%0,%1,%2,%3}, {%4,%5,%6,%7}, {%8,%9}, {%0,%1,%2,%3};"
                        : "+f"(c[i][j][0]), "+f"(c[i][j][1]),
                          "+f"(c[i][j][2]), "+f"(c[i][j][3])
                        : "r"(a[i][0]), "r"(a[i][1]), "r"(a[i][2]), "r"(a[i][3]),
                          "r"(b[j][0]), "r"(b[j][1]));
                }
        }
        stage(cch + NSTG - 1);
    }

    // ---- epilogue ----
#pragma unroll
    for (int i = 0; i < 4; i++) {
        int r0 = m0 + mw + i * 16 + g;
        int r1 = r0 + 8;
#pragma unroll
        for (int j = 0; j < NJ2; j++) {
            int n = n0 + nw + j * 8 + tg * 2;
            float bx = bias[n], by = bias[n + 1];
            float v0 = c[i][j][0] + bx, v1 = c[i][j][1] + by;
            float v2 = c[i][j][2] + bx, v3 = c[i][j][3] + by;
            if (GELU) {
                v0 = 0.5f * v0 * (1.f + erff(v0 * 0.70710678118654752f));
                v1 = 0.5f * v1 * (1.f + erff(v1 * 0.70710678118654752f));
                v2 = 0.5f * v2 * (1.f + erff(v2 * 0.70710678118654752f));
                v3 = 0.5f * v3 * (1.f + erff(v3 * 0.70710678118654752f));
            }
            if (r0 < M) {
                if (HOUT)
                    *(__half2*)&Ch[(size_t)r0 * ldch + n] = __floats2half2_rn(v0, v1);
                if (F32OUT) {
                    Cf[(size_t)r0 * ldcf + n]     = v0;
                    Cf[(size_t)r0 * ldcf + n + 1] = v1;
                }
            }
            if (r1 < M) {
                if (HOUT)
                    *(__half2*)&Ch[(size_t)r1 * ldch + n] = __floats2half2_rn(v2, v3);
                if (F32OUT) {
                    Cf[(size_t)r1 * ldcf + n]     = v2;
                    Cf[(size_t)r1 * ldcf + n + 1] = v3;
                }
            }
        }
    }
}

// ---------------- fp32 -> fp16 converter ------------------------------------
__global__ void cvth_kernel(const float* __restrict__ in, __half* __restrict__ out,
                            int n4)
{
    int i = blockIdx.x * blockDim.x + threadIdx.x;
    if (i >= n4) return;
    float4 v = *(const float4*)&in[i * 4];
    *(__half2*)&out[i * 4 + 0] = __floats2half2_rn(v.x, v.y);
    *(__half2*)&out[i * 4 + 2] = __floats2half2_rn(v.z, v.w);
}

// ---------------- su/sv: smem-staged, block = 16 nodes x 16 outputs ---------
// h rows read from g_cath (fp16, bit-exact: h values are half-rounded).
__global__ __launch_bounds__(256) void suv_kernel(const float* __restrict__ au_w,
                                                  const float* __restrict__ au_b,
                                                  const float* __restrict__ av_w)
{
    __shared__ float sw[16][132];
    __shared__ float sh[16][132];
    const int t  = threadIdx.x;
    const int n0 = blockIdx.x * 16;

    // stage 16 weight rows (au 0..7, av 8..15)
#pragma unroll
    for (int it = 0; it < 2; it++) {
        int q   = t + it * 256;        // 0..511
        int row = q >> 5;
        int i4  = (q & 31) << 2;
        const float* wsrc = (row < 8) ? &au_w[row * DIMD] : &av_w[(row - 8) * DIMD];
        *(float4*)&sw[row][i4] = *(const float4*)&wsrc[i4];
    }
    // stage 16 h rows from fp16 cath (convert to fp32 in smem)
#pragma unroll
    for (int it = 0; it < 2; it++) {
        int q   = t + it * 256;        // 0..511 ; each handles 4 halves
        int row = q >> 5;
        int i4  = (q & 31) << 2;
        const __half2* hp = (const __half2*)&g_cath[(size_t)(n0 + row) * CATD + i4];
        float2 f0 = __half22float2(hp[0]);
        float2 f1 = __half22float2(hp[1]);
        *(float4*)&sh[row][i4] = make_float4(f0.x, f0.y, f1.x, f1.y);
    }
    __syncthreads();

    const int nl = t >> 4;
    const int j  = t & 15;
    float s = 0.f;
#pragma unroll
    for (int i = 0; i < DIMD; i += 4) {
        float4 hv = *(const float4*)&sh[nl][i];
        float4 wv = *(const float4*)&sw[j][i];
        s += hv.x * wv.x + hv.y * wv.y + hv.z * wv.z + hv.w * wv.w;
    }
    if (j < 8) s += au_b[j];
    g_suv[(n0 + nl) * 16 + j] = s;
}

// ---------------- CSR build: degree histogram -------------------------------
__global__ void deg_kernel(const int* __restrict__ src,
                           const int* __restrict__ dst)
{
    int e = blockIdx.x * blockDim.x + threadIdx.x;
    if (e >= EE) return;
    atomicAdd(&g_din[dst[e]], 1);
    atomicAdd(&g_dout[src[e]], 1);
}

// ---------------- exclusive scan of g_din -> g_rowstart (single block) ------
__global__ __launch_bounds__(1024, 1) void scan_kernel()
{
    __shared__ int part[1024];
    const int t = threadIdx.x;
    const int PER = (NN + 1023) / 1024;   // 49
    const int base = t * PER;
    int s = 0;
    for (int i = 0; i < PER; i++) {
        int n = base + i;
        if (n < NN) s += g_din[n];
    }
    part[t] = s;
    __syncthreads();
    for (int off = 1; off < 1024; off <<= 1) {
        int v = (t >= off) ? part[t - off] : 0;
        __syncthreads();
        part[t] += v;
        __syncthreads();
    }
    int run = (t == 0) ? 0 : part[t - 1];
    for (int i = 0; i < PER; i++) {
        int n = base + i;
        if (n < NN) {
            g_rowstart[n] = run;
            run += g_din[n];
        }
    }
    if (t == 1023) g_rowstart[NN] = run;
}

// ---------------- fused scatter + edge score --------------------------------
__global__ void scatter_score_kernel(const int* __restrict__ src,
                                     const int* __restrict__ dst)
{
    int e = blockIdx.x * blockDim.x + threadIdx.x;
    if (e >= EE) return;
    int s = src[e], d = dst[e];
    int pos  = atomicAdd(&g_cursor[d], 1);
    int slot = g_rowstart[d] + pos;
    g_ssrc[slot] = s;

    const float* su = &g_suv[s * 16];
    const float* sv = &g_suv[d * 16 + 8];
    float ex[8];
#pragma unroll
    for (int k = 0; k < 8; k++) {
        float v = su[k] + sv[k];
        v = (v > 0.f) ? v : 0.2f * v;     // LeakyReLU(0.2)
        ex[k] = __expf(v);                // softmax shift-invariant: skip max
    }
    *(float4*)&g_ex[(size_t)slot * 8 + 0] = make_float4(ex[0], ex[1], ex[2], ex[3]);
    *(float4*)&g_ex[(size_t)slot * 8 + 4] = make_float4(ex[4], ex[5], ex[6], ex[7]);
    g_norm[slot] = rsqrtf((float)g_dout[s] * (float)g_dout[d]);
}

// ---------------- warp-per-dst fused aggregation (no atomics) ---------------
// h read as fp16 from g_cath cols 0..127 (bit-exact); writes fp16 msg blocks.
__global__ __launch_bounds__(256) void agg_kernel()
{
    int gw   = (blockIdx.x * blockDim.x + threadIdx.x) >> 5;
    int lane = threadIdx.x & 31;
    if (gw >= NN) return;
    const int d  = gw;
    const int r0 = g_rowstart[d];
    const int r1 = g_rowstart[d + 1];
    const int deg = r1 - r0;

    float den[8] = {0.f, 0.f, 0.f, 0.f, 0.f, 0.f, 0.f, 0.f};
    for (int i = r0 + lane; i < r1; i += 32) {
        float4 a = *(const float4*)&g_ex[(size_t)i * 8];
        float4 b = *(const float4*)&g_ex[(size_t)i * 8 + 4];
        den[0] += a.x; den[1] += a.y; den[2] += a.z; den[3] += a.w;
        den[4] += b.x; den[5] += b.y; den[6] += b.z; den[7] += b.w;
    }
#pragma unroll
    for (int k = 0; k < 8; k++)
#pragma unroll
        for (int off = 16; off; off >>= 1)
            den[k] += __shfl_xor_sync(0xFFFFFFFFu, den[k], off);

    const int d0 = lane * 4;
    const int kb = d0 & 7;
    float4 invden;
    invden.x = 1.f / den[kb + 0];
    invden.y = 1.f / den[kb + 1];
    invden.z = 1.f / den[kb + 2];
    invden.w = 1.f / den[kb + 3];

    float4 am = make_float4(0.f, 0.f, 0.f, 0.f);
    float4 as = make_float4(0.f, 0.f, 0.f, 0.f);
    float4 a3 = make_float4(0.f, 0.f, 0.f, 0.f);
#pragma unroll 2
    for (int i = r0; i < r1; i++) {
        int   s   = g_ssrc[i];
        float nrm = g_norm[i];
        float4 ex = *(const float4*)&g_ex[(size_t)i * 8 + kb];
        const __half2* hp = (const __half2*)&g_cath[(size_t)s * CATD + d0];
        float2 h01 = __half22float2(hp[0]);
        float2 h23 = __half22float2(hp[1]);
        am.x += h01.x * ex.x * invden.x;
        am.y += h01.y * ex.y * invden.y;
        am.z += h23.x * ex.z * invden.z;
        am.w += h23.y * ex.w * invden.w;
        as.x += h01.x; as.y += h01.y; as.z += h23.x; as.w += h23.y;
        a3.x += h01.x * nrm; a3.y += h01.y * nrm;
        a3.z += h23.x * nrm; a3.w += h23.y * nrm;
    }

    float invd = 1.f / fmaxf((float)deg, 1.f);
    __half* base = &g_cath[(size_t)d * CATD];
    *(__half2*)&base[128 + d0]     = __floats2half2_rn(am.x, am.y);
    *(__half2*)&base[128 + d0 + 2] = __floats2half2_rn(am.z, am.w);
    *(__half2*)&base[256 + d0]     = __floats2half2_rn(as.x * invd, as.y * invd);
    *(__half2*)&base[256 + d0 + 2] = __floats2half2_rn(as.z * invd, as.w * invd);
    *(__half2*)&base[384 + d0]     = __floats2half2_rn(a3.x, a3.y);
    *(__half2*)&base[384 + d0 + 2] = __floats2half2_rn(a3.z, a3.w);
}

// ---------------------------------------------------------------------------
extern "C" void kernel_launch(void* const* d_in, const int* in_sizes, int n_in,
                              void* d_out, int out_size)
{
    const float* x    = (const float*)d_in[0];
    const int*   src  = (const int*)d_in[1];
    const int*   dst  = (const int*)d_in[2];
    const float* fc_w = (const float*)d_in[3];
    const float* fc_b = (const float*)d_in[4];
    const float* au_w = (const float*)d_in[5];
    const float* au_b = (const float*)d_in[6];
    const float* av_w = (const float*)d_in[7];
    const float* w1   = (const float*)d_in[8];
    const float* b1   = (const float*)d_in[9];
    const float* w2   = (const float*)d_in[10];
    const float* b2   = (const float*)d_in[11];
    float* out = (float*)d_out;

    void *p_cath, *p_fh, *p_xh, *p_fcwh, *p_w1h, *p_w2h,
         *p_din, *p_dout, *p_cur;
    cudaGetSymbolAddress(&p_cath, g_cath);
    cudaGetSymbolAddress(&p_fh,   g_fh);
    cudaGetSymbolAddress(&p_xh,   g_xh);
    cudaGetSymbolAddress(&p_fcwh, g_fcwh);
    cudaGetSymbolAddress(&p_w1h,  g_w1h);
    cudaGetSymbolAddress(&p_w2h,  g_w2h);
    cudaGetSymbolAddress(&p_din,  g_din);
    cudaGetSymbolAddress(&p_dout, g_dout);
    cudaGetSymbolAddress(&p_cur,  g_cursor);

    cudaMemsetAsync(p_din,  0, sizeof(int) * NN, 0);
    cudaMemsetAsync(p_dout, 0, sizeof(int) * NN, 0);
    cudaMemsetAsync(p_cur,  0, sizeof(int) * NN, 0);

    __half* cath = (__half*)p_cath;
    __half* fh   = (__half*)p_fh;
    __half* xh   = (__half*)p_xh;
    __half* fcwh = (__half*)p_fcwh;
    __half* w1h  = (__half*)p_w1h;
    __half* w2h  = (__half*)p_w2h;

    const int sm128 = NSTG * (128 + 128) * LDS_P * 2;   // 147456
    const int sm256 = NSTG * (128 + 256) * LDS_P * 2;   // 221184
    cudaFuncSetAttribute((const void*)gemm_h<128, false, false, true>,
                         cudaFuncAttributeMaxDynamicSharedMemorySize, sm128);
    cudaFuncSetAttribute((const void*)gemm_h<256, true, false, true>,
                         cudaFuncAttributeMaxDynamicSharedMemorySize, sm256);
    cudaFuncSetAttribute((const void*)gemm_h<128, false, true, false>,
                         cudaFuncAttributeMaxDynamicSharedMemorySize, sm128);

    const int MB = (NN + 127) / 128;   // 391

    // pre-convert inputs to fp16
    cvth_kernel<<<(NN * DIMD / 4 + 255) / 256, 256>>>(x, xh, NN * DIMD / 4);
    cvth_kernel<<<(DIMD * DIMD / 4 + 255) / 256, 256>>>(fc_w, fcwh, DIMD * DIMD / 4);
    cvth_kernel<<<(HIDD * CATD / 4 + 255) / 256, 256>>>(w1, w1h, HIDD * CATD / 4);
    cvth_kernel<<<(DIMD * HIDD / 4 + 255) / 256, 256>>>(w2, w2h, DIMD * HIDD / 4);

    // CSR build (independent of h)
    deg_kernel<<<(EE + 255) / 256, 256>>>(src, dst);
    scan_kernel<<<1, 1024>>>();

    // h = x @ fc_w.T + fc_b  -> g_cath cols 0..127 (fp16 only)
    gemm_h<128, false, false, true><<<dim3(1, MB), 256, sm128>>>(
        xh, DIMD, fcwh, DIMD, fc_b, (float*)nullptr, 0, cath, CATD, NN, DIMD);
    // su/sv (smem-staged, fp16 h)
    suv_kernel<<<NN / 16, 256>>>(au_w, au_b, av_w);
    // fused scatter + edge scores + norm (slot order)
    scatter_score_kernel<<<(EE + 255) / 256, 256>>>(src, dst);
    // warp-per-dst aggregation -> g_cath cols 128..511 (fp16)
    agg_kernel<<<(NN * 32 + 255) / 256, 256>>>();
    // f = gelu(cat @ w1.T + b1) -> g_fh (fp16)
    gemm_h<256, true, false, true><<<dim3(HIDD / 256, MB), 256, sm256>>>(
        cath, CATD, w1h, CATD, b1, (float*)nullptr, 0, fh, HIDD, NN, CATD);
    // out = f @ w2.T + b2 (fp32)
    gemm_h<128, false, true, false><<<dim3(DIMD / 128, MB), 256, sm128>>>(
        fh, HIDD, w2h, HIDD, b2, out, DIMD, (__half*)nullptr, 0, NN, HIDD);
}

// round 13
// speedup vs baseline: 1.5124x; 1.5124x over previous
#include <cuda_runtime.h>
#include <cuda_fp16.h>
#include <cstdint>
#include <math.h>

#define NN   50000
#define EE   800000
#define DIMD 128
#define CATD 512
#define HIDD 512

// ---------------- scratch (device globals; no allocations allowed) ----------
__device__ __align__(16) float  g_h[(size_t)NN * DIMD];     // h fp32 (half-rounded)
__device__ __align__(16) __half g_cath[(size_t)NN * CATD];  // [h|msg|msg2|msg3] half
__device__ __align__(16) __half g_fh[(size_t)NN * HIDD];    // gelu(...) half
__device__ __align__(16) __half g_xh[(size_t)NN * DIMD];
__device__ __align__(16) __half g_fcwh[DIMD * DIMD];
__device__ __align__(16) __half g_w1h[HIDD * CATD];
__device__ __align__(16) __half g_w2h[DIMD * HIDD];
__device__ __align__(16) float  g_suv[NN * 16];             // su[0..7], sv[8..15]
__device__ __align__(16) float  g_ex[(size_t)EE * 8];       // exp scores, SLOT order
__device__ float g_norm[EE];
__device__ int   g_din[NN];
__device__ int   g_dout[NN];
__device__ int   g_rowstart[NN + 1];
__device__ int   g_cursor[NN];
__device__ int   g_ssrc[EE];

__device__ __forceinline__ float rhalf(float x) {
    return __half2float(__float2half_rn(x));
}

__device__ __forceinline__ void cpa16(uint32_t dst, const void* src, int pbytes) {
    asm volatile("cp.async.cg.shared.global [%0], [%1], 16, %2;"
                 :: "r"(dst), "l"(src), "r"(pbytes));
}
__device__ __forceinline__ void cpa_commit() {
    asm volatile("cp.async.commit_group;");
}
template <int NG>
__device__ __forceinline__ void cpa_wait() {
    asm volatile("cp.async.wait_group %0;" :: "n"(NG));
}

// ---------------- fp16 mma.sync GEMM: C = A[M,K] @ B[N,K]^T + bias ----------
// CTA 128(M) x NT(N), K-chunk 64 halves, NSTGP-stage cp.async pipeline.
#define KCH   64
#define LDS_P 72      // halves per row (64 + 8 pad); conflict-free frag LDS

template <int NT, int NSTGP, int MINB, bool GELU, bool F32OUT, bool HOUT, bool RND>
__global__ __launch_bounds__(256, MINB) void gemm_h(
    const __half* __restrict__ A, int lda,
    const __half* __restrict__ B, int ldb,
    const float* __restrict__ bias,
    float* __restrict__ Cf, int ldcf,
    __half* __restrict__ Ch, int ldch,
    int M, int K)
{
    constexpr int ASZ = 128 * LDS_P;         // halves per stage
    constexpr int BSZ = NT  * LDS_P;
    constexpr int NJ2 = NT / 32;             // b-frag count (4 or 8)
    extern __shared__ __half smh[];

    const int tid  = threadIdx.x;
    const int wid  = tid >> 5, lane = tid & 31;
    const int g    = lane >> 2;
    const int tg   = lane & 3;
    const int m0   = blockIdx.y * 128;
    const int n0   = blockIdx.x * NT;
    const int mw   = (wid >> 2) * 64;
    const int nw   = (wid & 3) * (NT / 4);

    float c[4][NJ2][4];
#pragma unroll
    for (int i = 0; i < 4; i++)
#pragma unroll
        for (int j = 0; j < NJ2; j++)
#pragma unroll
            for (int q = 0; q < 4; q++) c[i][j][q] = 0.f;

    const int KC = K / KCH;

    auto stage = [&](int cc) {
        if (cc < KC) {
            const int kc = cc * KCH;
            __half* sA = smh + (cc % NSTGP) * (ASZ + BSZ);
            __half* sB = sA + ASZ;
            uint32_t sAu = (uint32_t)__cvta_generic_to_shared(sA);
            uint32_t sBu = (uint32_t)__cvta_generic_to_shared(sB);
#pragma unroll
            for (int it = 0; it < 4; it++) {           // 128 rows x 8x16B
                int q   = tid + it * 256;
                int row = q >> 3;
                int kq  = (q & 7) << 3;                // half offset
                int m   = m0 + row;
                int ok  = (m < M) ? 16 : 0;
                const __half* srcp = &A[(size_t)(ok ? m : 0) * lda + kc + kq];
                cpa16(sAu + (row * LDS_P + kq) * 2, srcp, ok);
            }
#pragma unroll
            for (int it = 0; it < NT / 32; it++) {     // NT rows x 8x16B
                int q   = tid + it * 256;
                int row = q >> 3;
                int kq  = (q & 7) << 3;
                cpa16(sBu + (row * LDS_P + kq) * 2,
                      &B[(size_t)(n0 + row) * ldb + kc + kq], 16);
            }
        }
        cpa_commit();
    };

#pragma unroll
    for (int s = 0; s < NSTGP - 1; s++) stage(s);

    for (int cch = 0; cch < KC; cch++) {
        cpa_wait<NSTGP - 2>();
        __syncthreads();

        const __half* sA = smh + (cch % NSTGP) * (ASZ + BSZ);
        const __half* sB = sA + ASZ;
        const uint32_t* uA = (const uint32_t*)sA;      // 2 halves per u32
        const uint32_t* uB = (const uint32_t*)sB;
#pragma unroll
        for (int ks = 0; ks < KCH / 16; ks++) {        // 4 k16 steps
            uint32_t a[4][4], b[NJ2][2];
#pragma unroll
            for (int i = 0; i < 4; i++) {
                int r  = (mw + i * 16 + g) * (LDS_P / 2) + ks * 8 + tg;
                a[i][0] = uA[r];
                a[i][1] = uA[r + 8 * (LDS_P / 2)];
                a[i][2] = uA[r + 4];
                a[i][3] = uA[r + 8 * (LDS_P / 2) + 4];
            }
#pragma unroll
            for (int j = 0; j < NJ2; j++) {
                int r = (nw + j * 8 + g) * (LDS_P / 2) + ks * 8 + tg;
                b[j][0] = uB[r];
                b[j][1] = uB[r + 4];
            }
#pragma unroll
            for (int i = 0; i < 4; i++)
#pragma unroll
                for (int j = 0; j < NJ2; j++) {
                    asm volatile(
                        "mma.sync.aligned.m16n8k16.row.col.f32.f16.f16.f32 "
                        "{%0,%1,%2,%3}, {%4,%5,%6,%7}, {%8,%9}, {%0,%1,%2,%3};"
                        : "+f"(c[i][j][0]), "+f"(c[i][j][1]),
                          "+f"(c[i][j][2]), "+f"(c[i][j][3])
                        : "r"(a[i][0]), "r"(a[i][1]), "r"(a[i][2]), "r"(a[i][3]),
                          "r"(b[j][0]), "r"(b[j][1]));
                }
        }
        stage(cch + NSTGP - 1);
    }

    // ---- epilogue ----
#pragma unroll
    for (int i = 0; i < 4; i++) {
        int r0 = m0 + mw + i * 16 + g;
        int r1 = r0 + 8;
#pragma unroll
        for (int j = 0; j < NJ2; j++) {
            int n = n0 + nw + j * 8 + tg * 2;
            float bx = bias[n], by = bias[n + 1];
            float v0 = c[i][j][0] + bx, v1 = c[i][j][1] + by;
            float v2 = c[i][j][2] + bx, v3 = c[i][j][3] + by;
            if (GELU) {
                v0 = 0.5f * v0 * (1.f + erff(v0 * 0.70710678118654752f));
                v1 = 0.5f * v1 * (1.f + erff(v1 * 0.70710678118654752f));
                v2 = 0.5f * v2 * (1.f + erff(v2 * 0.70710678118654752f));
                v3 = 0.5f * v3 * (1.f + erff(v3 * 0.70710678118654752f));
            }
            if (r0 < M) {
                if (HOUT)
                    *(__half2*)&Ch[(size_t)r0 * ldch + n] = __floats2half2_rn(v0, v1);
                if (F32OUT) {
                    Cf[(size_t)r0 * ldcf + n]     = RND ? rhalf(v0) : v0;
                    Cf[(size_t)r0 * ldcf + n + 1] = RND ? rhalf(v1) : v1;
                }
            }
            if (r1 < M) {
                if (HOUT)
                    *(__half2*)&Ch[(size_t)r1 * ldch + n] = __floats2half2_rn(v2, v3);
                if (F32OUT) {
                    Cf[(size_t)r1 * ldcf + n]     = RND ? rhalf(v2) : v2;
                    Cf[(size_t)r1 * ldcf + n + 1] = RND ? rhalf(v3) : v3;
                }
            }
        }
    }
}

// ---------------- fp32 -> fp16 converter ------------------------------------
__global__ void cvth_kernel(const float* __restrict__ in, __half* __restrict__ out,
                            int n4)
{
    int i = blockIdx.x * blockDim.x + threadIdx.x;
    if (i >= n4) return;
    float4 v = *(const float4*)&in[i * 4];
    *(__half2*)&out[i * 4 + 0] = __floats2half2_rn(v.x, v.y);
    *(__half2*)&out[i * 4 + 2] = __floats2half2_rn(v.z, v.w);
}

// ---------------- su/sv: smem-staged, block = 16 nodes x 16 outputs ---------
__global__ __launch_bounds__(256) void suv_kernel(const float* __restrict__ au_w,
                                                  const float* __restrict__ au_b,
                                                  const float* __restrict__ av_w)
{
    __shared__ float sw[16][132];
    __shared__ float sh[16][132];
    const int t  = threadIdx.x;
    const int n0 = blockIdx.x * 16;

#pragma unroll
    for (int it = 0; it < 2; it++) {
        int q   = t + it * 256;        // 0..511
        int row = q >> 5;
        int i4  = (q & 31) << 2;
        const float* wsrc = (row < 8) ? &au_w[row * DIMD] : &av_w[(row - 8) * DIMD];
        *(float4*)&sw[row][i4] = *(const float4*)&wsrc[i4];
    }
#pragma unroll
    for (int it = 0; it < 2; it++) {
        int q   = t + it * 256;
        int row = q >> 5;
        int i4  = (q & 31) << 2;
        *(float4*)&sh[row][i4] = *(const float4*)&g_h[(size_t)(n0 + row) * DIMD + i4];
    }
    __syncthreads();

    const int nl = t >> 4;
    const int j  = t & 15;
    float s = 0.f;
#pragma unroll
    for (int i = 0; i < DIMD; i += 4) {
        float4 hv = *(const float4*)&sh[nl][i];
        float4 wv = *(const float4*)&sw[j][i];
        s += hv.x * wv.x + hv.y * wv.y + hv.z * wv.z + hv.w * wv.w;
    }
    if (j < 8) s += au_b[j];
    g_suv[(n0 + nl) * 16 + j] = s;
}

// ---------------- CSR build: degree histogram -------------------------------
__global__ void deg_kernel(const int* __restrict__ src,
                           const int* __restrict__ dst)
{
    int e = blockIdx.x * blockDim.x + threadIdx.x;
    if (e >= EE) return;
    atomicAdd(&g_din[dst[e]], 1);
    atomicAdd(&g_dout[src[e]], 1);
}

// ---------------- exclusive scan of g_din -> g_rowstart (single block) ------
__global__ __launch_bounds__(1024, 1) void scan_kernel()
{
    __shared__ int part[1024];
    const int t = threadIdx.x;
    const int PER = (NN + 1023) / 1024;   // 49
    const int base = t * PER;
    int s = 0;
    for (int i = 0; i < PER; i++) {
        int n = base + i;
        if (n < NN) s += g_din[n];
    }
    part[t] = s;
    __syncthreads();
    for (int off = 1; off < 1024; off <<= 1) {
        int v = (t >= off) ? part[t - off] : 0;
        __syncthreads();
        part[t] += v;
        __syncthreads();
    }
    int run = (t == 0) ? 0 : part[t - 1];
    for (int i = 0; i < PER; i++) {
        int n = base + i;
        if (n < NN) {
            g_rowstart[n] = run;
            run += g_din[n];
        }
    }
    if (t == 1023) g_rowstart[NN] = run;
}

// ---------------- fused scatter + edge score --------------------------------
__global__ void scatter_score_kernel(const int* __restrict__ src,
                                     const int* __restrict__ dst)
{
    int e = blockIdx.x * blockDim.x + threadIdx.x;
    if (e >= EE) return;
    int s = src[e], d = dst[e];
    int pos  = atomicAdd(&g_cursor[d], 1);
    int slot = g_rowstart[d] + pos;
    g_ssrc[slot] = s;

    const float* su = &g_suv[s * 16];
    const float* sv = &g_suv[d * 16 + 8];
    float ex[8];
#pragma unroll
    for (int k = 0; k < 8; k++) {
        float v = su[k] + sv[k];
        v = (v > 0.f) ? v : 0.2f * v;     // LeakyReLU(0.2)
        ex[k] = __expf(v);                // softmax shift-invariant: skip max
    }
    *(float4*)&g_ex[(size_t)slot * 8 + 0] = make_float4(ex[0], ex[1], ex[2], ex[3]);
    *(float4*)&g_ex[(size_t)slot * 8 + 4] = make_float4(ex[4], ex[5], ex[6], ex[7]);
    g_norm[slot] = rsqrtf((float)g_dout[s] * (float)g_dout[d]);
}

// ---------------- warp-per-dst fused aggregation (no atomics) ---------------
// Reads fp32 g_h (one LDG.128 per lane per edge — keep MLP), writes fp16 msgs.
__global__ __launch_bounds__(256) void agg_kernel()
{
    int gw   = (blockIdx.x * blockDim.x + threadIdx.x) >> 5;
    int lane = threadIdx.x & 31;
    if (gw >= NN) return;
    const int d  = gw;
    const int r0 = g_rowstart[d];
    const int r1 = g_rowstart[d + 1];
    const int deg = r1 - r0;

    float den[8] = {0.f, 0.f, 0.f, 0.f, 0.f, 0.f, 0.f, 0.f};
    for (int i = r0 + lane; i < r1; i += 32) {
        float4 a = *(const float4*)&g_ex[(size_t)i * 8];
        float4 b = *(const float4*)&g_ex[(size_t)i * 8 + 4];
        den[0] += a.x; den[1] += a.y; den[2] += a.z; den[3] += a.w;
        den[4] += b.x; den[5] += b.y; den[6] += b.z; den[7] += b.w;
    }
#pragma unroll
    for (int k = 0; k < 8; k++)
#pragma unroll
        for (int off = 16; off; off >>= 1)
            den[k] += __shfl_xor_sync(0xFFFFFFFFu, den[k], off);

    const int d0 = lane * 4;
    const int kb = d0 & 7;
    float4 invden;
    invden.x = 1.f / den[kb + 0];
    invden.y = 1.f / den[kb + 1];
    invden.z = 1.f / den[kb + 2];
    invden.w = 1.f / den[kb + 3];

    float4 am = make_float4(0.f, 0.f, 0.f, 0.f);
    float4 as = make_float4(0.f, 0.f, 0.f, 0.f);
    float4 a3 = make_float4(0.f, 0.f, 0.f, 0.f);
#pragma unroll 2
    for (int i = r0; i < r1; i++) {
        int   s   = g_ssrc[i];
        float nrm = g_norm[i];
        float4 ex = *(const float4*)&g_ex[(size_t)i * 8 + kb];
        float4 h  = *(const float4*)&g_h[(size_t)s * DIMD + d0];
        am.x += h.x * ex.x * invden.x;
        am.y += h.y * ex.y * invden.y;
        am.z += h.z * ex.z * invden.z;
        am.w += h.w * ex.w * invden.w;
        as.x += h.x; as.y += h.y; as.z += h.z; as.w += h.w;
        a3.x += h.x * nrm; a3.y += h.y * nrm;
        a3.z += h.z * nrm; a3.w += h.w * nrm;
    }

    float invd = 1.f / fmaxf((float)deg, 1.f);
    __half* base = &g_cath[(size_t)d * CATD];
    *(__half2*)&base[128 + d0]     = __floats2half2_rn(am.x, am.y);
    *(__half2*)&base[128 + d0 + 2] = __floats2half2_rn(am.z, am.w);
    *(__half2*)&base[256 + d0]     = __floats2half2_rn(as.x * invd, as.y * invd);
    *(__half2*)&base[256 + d0 + 2] = __floats2half2_rn(as.z * invd, as.w * invd);
    *(__half2*)&base[384 + d0]     = __floats2half2_rn(a3.x, a3.y);
    *(__half2*)&base[384 + d0 + 2] = __floats2half2_rn(a3.z, a3.w);
}

// ---------------------------------------------------------------------------
extern "C" void kernel_launch(void* const* d_in, const int* in_sizes, int n_in,
                              void* d_out, int out_size)
{
    const float* x    = (const float*)d_in[0];
    const int*   src  = (const int*)d_in[1];
    const int*   dst  = (const int*)d_in[2];
    const float* fc_w = (const float*)d_in[3];
    const float* fc_b = (const float*)d_in[4];
    const float* au_w = (const float*)d_in[5];
    const float* au_b = (const float*)d_in[6];
    const float* av_w = (const float*)d_in[7];
    const float* w1   = (const float*)d_in[8];
    const float* b1   = (const float*)d_in[9];
    const float* w2   = (const float*)d_in[10];
    const float* b2   = (const float*)d_in[11];
    float* out = (float*)d_out;

    void *p_h, *p_cath, *p_fh, *p_xh, *p_fcwh, *p_w1h, *p_w2h,
         *p_din, *p_dout, *p_cur;
    cudaGetSymbolAddress(&p_h,    g_h);
    cudaGetSymbolAddress(&p_cath, g_cath);
    cudaGetSymbolAddress(&p_fh,   g_fh);
    cudaGetSymbolAddress(&p_xh,   g_xh);
    cudaGetSymbolAddress(&p_fcwh, g_fcwh);
    cudaGetSymbolAddress(&p_w1h,  g_w1h);
    cudaGetSymbolAddress(&p_w2h,  g_w2h);
    cudaGetSymbolAddress(&p_din,  g_din);
    cudaGetSymbolAddress(&p_dout, g_dout);
    cudaGetSymbolAddress(&p_cur,  g_cursor);

    cudaMemsetAsync(p_din,  0, sizeof(int) * NN, 0);
    cudaMemsetAsync(p_dout, 0, sizeof(int) * NN, 0);
    cudaMemsetAsync(p_cur,  0, sizeof(int) * NN, 0);

    float*  hbuf = (float*)p_h;
    __half* cath = (__half*)p_cath;
    __half* fh   = (__half*)p_fh;
    __half* xh   = (__half*)p_xh;
    __half* fcwh = (__half*)p_fcwh;
    __half* w1h  = (__half*)p_w1h;
    __half* w2h  = (__half*)p_w2h;

    const int sm128 = 3 * (128 + 128) * LDS_P * 2;   // 110592 -> 2 CTAs/SM
    const int sm256 = 4 * (128 + 256) * LDS_P * 2;   // 221184 -> 1 CTA/SM
    cudaFuncSetAttribute((const void*)gemm_h<128, 3, 2, false, true, true, true>,
                         cudaFuncAttributeMaxDynamicSharedMemorySize, sm128);
    cudaFuncSetAttribute((const void*)gemm_h<256, 4, 1, true, false, true, false>,
                         cudaFuncAttributeMaxDynamicSharedMemorySize, sm256);
    cudaFuncSetAttribute((const void*)gemm_h<128, 3, 2, false, true, false, false>,
                         cudaFuncAttributeMaxDynamicSharedMemorySize, sm128);

    const int MB = (NN + 127) / 128;   // 391

    // pre-convert inputs to fp16
    cvth_kernel<<<(NN * DIMD / 4 + 255) / 256, 256>>>(x, xh, NN * DIMD / 4);
    cvth_kernel<<<(DIMD * DIMD / 4 + 255) / 256, 256>>>(fc_w, fcwh, DIMD * DIMD / 4);
    cvth_kernel<<<(HIDD * CATD / 4 + 255) / 256, 256>>>(w1, w1h, HIDD * CATD / 4);
    cvth_kernel<<<(DIMD * HIDD / 4 + 255) / 256, 256>>>(w2, w2h, DIMD * HIDD / 4);

    // CSR build (independent of h)
    deg_kernel<<<(EE + 255) / 256, 256>>>(src, dst);
    scan_kernel<<<1, 1024>>>();

    // h = x @ fc_w.T + fc_b  -> g_h (fp32, half-rounded) + g_cath cols 0..127
    gemm_h<128, 3, 2, false, true, true, true><<<dim3(1, MB), 256, sm128>>>(
        xh, DIMD, fcwh, DIMD, fc_b, hbuf, DIMD, cath, CATD, NN, DIMD);
    // su/sv (smem-staged)
    suv_kernel<<<NN / 16, 256>>>(au_w, au_b, av_w);
    // fused scatter + edge scores + norm (slot order)
    scatter_score_kernel<<<(EE + 255) / 256, 256>>>(src, dst);
    // warp-per-dst aggregation -> g_cath cols 128..511 (fp16)
    agg_kernel<<<(NN * 32 + 255) / 256, 256>>>();
    // f = gelu(cat @ w1.T + b1) -> g_fh (fp16)
    gemm_h<256, 4, 1, true, false, true, false><<<dim3(HIDD / 256, MB), 256, sm256>>>(
        cath, CATD, w1h, CATD, b1, (float*)nullptr, 0, fh, HIDD, NN, CATD);
    // out = f @ w2.T + b2 (fp32)
    gemm_h<128, 3, 2, false, true, false, false><<<dim3(DIMD / 128, MB), 256, sm128>>>(
        fh, HIDD, w2h, HIDD, b2, out, DIMD, (__half*)nullptr, 0, NN, HIDD);
}